// round 10
// baseline (speedup 1.0000x reference)
#include <cuda_runtime.h>
#include <stdint.h>

// ---------------------------------------------------------------------------
// FakeQuant (global min/max), split kernels:
//
//   reduce (forward):  low region __ldcs (streaming), top ~112MB default
//                      (stays L2-resident for the apply pass). Last-finishing
//                      block (atomic counter, self-resetting for graph replay)
//                      folds all per-block partials into g_final using ONE
//                      warp (no extra block-wide barriers on the critical path).
//   apply  (backward): reads g_final (2 words), then streams 4-wide:
//                      __ldcs reads (top region hits L2 first), __stcs writes.
//                      ONE exact resident wave: 888 blocks @ 6 blocks/SM
//                      (__launch_bounds__(256,6) caps regs at 42).
//
//   out = rint((x - mn)*scale)/scale + mn,  scale = 255/(mx - mn)
//   (clip(x, min(x), max(x)) == x, dropped.)
// ---------------------------------------------------------------------------

#define RED_BLOCKS (148 * 8)   // 1184 reduce blocks
#define APP_BLOCKS (148 * 6)   // 888 apply blocks = one exact wave at occ 6
#define TPB 256

__device__ float2       g_partials[RED_BLOCKS];  // .x = min, .y = max
__device__ float2       g_final;                 // folded (min, max)
__device__ unsigned int g_done_count = 0;        // self-resetting

__device__ __forceinline__ void acc4(float4 v, float& mn, float& mx) {
    mn = fminf(mn, fminf(fminf(v.x, v.y), fminf(v.z, v.w)));
    mx = fmaxf(mx, fmaxf(fmaxf(v.x, v.y), fmaxf(v.z, v.w)));
}

__device__ __forceinline__ float4 fq4(float4 v, float mn, float scale, float inv) {
    float4 r;
    r.x = fmaf(rintf((v.x - mn) * scale), inv, mn);
    r.y = fmaf(rintf((v.y - mn) * scale), inv, mn);
    r.z = fmaf(rintf((v.z - mn) * scale), inv, mn);
    r.w = fmaf(rintf((v.w - mn) * scale), inv, mn);
    return r;
}

// ---------------- reduce: forward sweep --------------------------------------
__global__ void __launch_bounds__(TPB) minmax_reduce_kernel(
    const float4* __restrict__ x4, int n4, int keep_thresh) {
    float mn = 3.402823466e+38f;
    float mx = -3.402823466e+38f;

    const int S = gridDim.x * blockDim.x;
    int i = blockIdx.x * blockDim.x + threadIdx.x;

    // Low region: streaming loads.
    for (; i + 3 * S < keep_thresh; i += 4 * S) {
        float4 a = __ldcs(&x4[i]);
        float4 b = __ldcs(&x4[i + S]);
        float4 c = __ldcs(&x4[i + 2 * S]);
        float4 d = __ldcs(&x4[i + 3 * S]);
        acc4(a, mn, mx); acc4(b, mn, mx); acc4(c, mn, mx); acc4(d, mn, mx);
    }
    for (; i < keep_thresh; i += S) acc4(__ldcs(&x4[i]), mn, mx);

    // Top region: default policy — stays in L2 for apply.
    for (; i + 3 * S < n4; i += 4 * S) {
        float4 a = x4[i];
        float4 b = x4[i + S];
        float4 c = x4[i + 2 * S];
        float4 d = x4[i + 3 * S];
        acc4(a, mn, mx); acc4(b, mn, mx); acc4(c, mn, mx); acc4(d, mn, mx);
    }
    for (; i < n4; i += S) acc4(x4[i], mn, mx);

    // warp + block reduce
    #pragma unroll
    for (int off = 16; off > 0; off >>= 1) {
        mn = fminf(mn, __shfl_xor_sync(0xFFFFFFFFu, mn, off));
        mx = fmaxf(mx, __shfl_xor_sync(0xFFFFFFFFu, mx, off));
    }
    __shared__ float s_mn[TPB / 32];
    __shared__ float s_mx[TPB / 32];
    int wid = threadIdx.x >> 5;
    int lid = threadIdx.x & 31;
    if (lid == 0) { s_mn[wid] = mn; s_mx[wid] = mx; }
    __syncthreads();
    __shared__ bool s_last;
    if (wid == 0) {
        const int nw = TPB / 32;
        mn = (lid < nw) ? s_mn[lid] : 3.402823466e+38f;
        mx = (lid < nw) ? s_mx[lid] : -3.402823466e+38f;
        #pragma unroll
        for (int off = 4; off > 0; off >>= 1) {
            mn = fminf(mn, __shfl_xor_sync(0xFFFFFFFFu, mn, off));
            mx = fmaxf(mx, __shfl_xor_sync(0xFFFFFFFFu, mx, off));
        }
        if (lid == 0) {
            g_partials[blockIdx.x] = make_float2(mn, mx);
            __threadfence();                              // publish partial
            unsigned int prev = atomicAdd(&g_done_count, 1u);
            s_last = (prev == (unsigned int)(gridDim.x - 1));
            if (s_last) g_done_count = 0;                 // reset for replay
        }
        // Last-finishing block: warp 0 alone folds all partials into g_final.
        s_last = __shfl_sync(0xFFFFFFFFu, s_last, 0);
        if (s_last) {
            float fmn = 3.402823466e+38f;
            float fmx = -3.402823466e+38f;
            for (int p = lid; p < RED_BLOCKS; p += 32) {
                float2 v = g_partials[p];
                fmn = fminf(fmn, v.x);
                fmx = fmaxf(fmx, v.y);
            }
            #pragma unroll
            for (int off = 16; off > 0; off >>= 1) {
                fmn = fminf(fmn, __shfl_xor_sync(0xFFFFFFFFu, fmn, off));
                fmx = fmaxf(fmx, __shfl_xor_sync(0xFFFFFFFFu, fmx, off));
            }
            if (lid == 0) g_final = make_float2(fmn, fmx);
        }
    }
}

// ---------------- apply: backward sweep, 4-wide, one exact wave -------------
__global__ void __launch_bounds__(TPB, 6) fakequant_apply_kernel(
    const float4* __restrict__ x4, float4* __restrict__ out4, int n4) {
    const float2 f = g_final;          // 2-word L2-broadcast read
    const float mn    = f.x;
    const float scale = 255.0f / (f.y - f.x);
    const float inv   = 1.0f / scale;

    const int S = gridDim.x * blockDim.x;
    const int gtid = blockIdx.x * blockDim.x + threadIdx.x;
    if (gtid >= n4) return;

    int k = (n4 - 1 - gtid) / S;  // highest valid stride index for this thread

    for (; k >= 3; k -= 4) {
        int i0 = gtid + k * S;
        int i1 = i0 - S;
        int i2 = i0 - 2 * S;
        int i3 = i0 - 3 * S;
        float4 a = __ldcs(&x4[i0]);
        float4 b = __ldcs(&x4[i1]);
        float4 c = __ldcs(&x4[i2]);
        float4 d = __ldcs(&x4[i3]);
        __stcs(&out4[i0], fq4(a, mn, scale, inv));
        __stcs(&out4[i1], fq4(b, mn, scale, inv));
        __stcs(&out4[i2], fq4(c, mn, scale, inv));
        __stcs(&out4[i3], fq4(d, mn, scale, inv));
    }
    for (; k >= 0; --k) {
        int i0 = gtid + k * S;
        __stcs(&out4[i0], fq4(__ldcs(&x4[i0]), mn, scale, inv));
    }
}

// Scalar tail (never hit for this shape: n % 1024 == 0; kept for generality).
__global__ void fakequant_tail_kernel(const float* __restrict__ x,
                                      float* __restrict__ out,
                                      int start, int n) {
    float2 f = g_final;
    const float mn    = f.x;
    const float scale = 255.0f / (f.y - f.x);
    const float inv   = 1.0f / scale;
    int i = start + blockIdx.x * blockDim.x + threadIdx.x;
    if (i < n) out[i] = fmaf(rintf((x[i] - mn) * scale), inv, mn);
}

extern "C" void kernel_launch(void* const* d_in, const int* in_sizes, int n_in,
                              void* d_out, int out_size) {
    const float* x = (const float*)d_in[0];
    float* out = (float*)d_out;
    int n = in_sizes[0];
    int n4 = n >> 2;
    int tail_start = n4 << 2;

    // Keep the TOP ~112MB of x default-policy in reduce (L2 is ~126MB).
    const long long KEEP_BYTES = 112LL * 1024 * 1024;
    int keep_elems = (int)(KEEP_BYTES / 16);  // float4s
    int keep_thresh = n4 > keep_elems ? n4 - keep_elems : 0;

    minmax_reduce_kernel<<<RED_BLOCKS, TPB>>>((const float4*)x, n4, keep_thresh);
    fakequant_apply_kernel<<<APP_BLOCKS, TPB>>>((const float4*)x, (float4*)out, n4);

    if (tail_start < n) {
        int tail = n - tail_start;
        fakequant_tail_kernel<<<(tail + TPB - 1) / TPB, TPB>>>(x, out, tail_start, n);
    }
}

// round 11
// speedup vs baseline: 1.0389x; 1.0389x over previous
#include <cuda_runtime.h>
#include <stdint.h>

// ---------------------------------------------------------------------------
// FakeQuant (global min/max), split kernels — no init kernel, no fold pass:
//
//   Global min/max live in two order-preserving uint words (flip trick),
//   statically initialized to sentinels at module load. Each reduce block
//   folds its block-local (mn,mx) with ONE atomicMin + ONE atomicMax.
//   The LAST-finishing apply block (atomic done-counter, self-resetting)
//   restores the sentinels for the next CUDA-graph replay — safe because
//   every apply block reads the bits at its start and increments the counter
//   only at its end.
//
//   reduce (forward):  low region __ldcs (streaming), top ~112MB default
//                      (stays L2-resident for the apply pass)
//   apply  (backward): __ldcs reads (top region hits L2 first), __stcs writes,
//                      4-wide, 1184 blocks (measured-best geometry, 59.4us)
//
//   out = rint((x - mn)*scale)/scale + mn,  scale = 255/(mx - mn)
//   (clip(x, min(x), max(x)) == x, dropped.)
// ---------------------------------------------------------------------------

#define RED_BLOCKS (148 * 8)   // 1184
#define APP_BLOCKS (148 * 8)   // 1184 (measured best for apply)
#define TPB 256

// Order-preserving float<->uint mapping sentinels (min over flipped = all-1s).
__device__ unsigned int g_min_bits = 0xFFFFFFFFu;
__device__ unsigned int g_max_bits = 0x00000000u;
__device__ unsigned int g_app_done = 0;          // self-resetting

__device__ __forceinline__ unsigned int flip_f2u(float f) {
    unsigned int b = __float_as_uint(f);
    return (b & 0x80000000u) ? ~b : (b | 0x80000000u);
}
__device__ __forceinline__ float unflip_u2f(unsigned int b) {
    unsigned int r = (b & 0x80000000u) ? (b & 0x7FFFFFFFu) : ~b;
    return __uint_as_float(r);
}

__device__ __forceinline__ void acc4(float4 v, float& mn, float& mx) {
    mn = fminf(mn, fminf(fminf(v.x, v.y), fminf(v.z, v.w)));
    mx = fmaxf(mx, fmaxf(fmaxf(v.x, v.y), fmaxf(v.z, v.w)));
}

__device__ __forceinline__ float4 fq4(float4 v, float mn, float scale, float inv) {
    float4 r;
    r.x = fmaf(rintf((v.x - mn) * scale), inv, mn);
    r.y = fmaf(rintf((v.y - mn) * scale), inv, mn);
    r.z = fmaf(rintf((v.z - mn) * scale), inv, mn);
    r.w = fmaf(rintf((v.w - mn) * scale), inv, mn);
    return r;
}

// ---------------- reduce: forward sweep --------------------------------------
__global__ void __launch_bounds__(TPB) minmax_reduce_kernel(
    const float4* __restrict__ x4, int n4, int keep_thresh) {
    float mn = 3.402823466e+38f;
    float mx = -3.402823466e+38f;

    const int S = gridDim.x * blockDim.x;
    int i = blockIdx.x * blockDim.x + threadIdx.x;

    // Low region: streaming loads.
    for (; i + 3 * S < keep_thresh; i += 4 * S) {
        float4 a = __ldcs(&x4[i]);
        float4 b = __ldcs(&x4[i + S]);
        float4 c = __ldcs(&x4[i + 2 * S]);
        float4 d = __ldcs(&x4[i + 3 * S]);
        acc4(a, mn, mx); acc4(b, mn, mx); acc4(c, mn, mx); acc4(d, mn, mx);
    }
    for (; i < keep_thresh; i += S) acc4(__ldcs(&x4[i]), mn, mx);

    // Top region: default policy — stays in L2 for apply.
    for (; i + 3 * S < n4; i += 4 * S) {
        float4 a = x4[i];
        float4 b = x4[i + S];
        float4 c = x4[i + 2 * S];
        float4 d = x4[i + 3 * S];
        acc4(a, mn, mx); acc4(b, mn, mx); acc4(c, mn, mx); acc4(d, mn, mx);
    }
    for (; i < n4; i += S) acc4(x4[i], mn, mx);

    // warp + block reduce, then ONE atomic pair per block.
    #pragma unroll
    for (int off = 16; off > 0; off >>= 1) {
        mn = fminf(mn, __shfl_xor_sync(0xFFFFFFFFu, mn, off));
        mx = fmaxf(mx, __shfl_xor_sync(0xFFFFFFFFu, mx, off));
    }
    __shared__ float s_mn[TPB / 32];
    __shared__ float s_mx[TPB / 32];
    int wid = threadIdx.x >> 5;
    int lid = threadIdx.x & 31;
    if (lid == 0) { s_mn[wid] = mn; s_mx[wid] = mx; }
    __syncthreads();
    if (wid == 0) {
        const int nw = TPB / 32;
        mn = (lid < nw) ? s_mn[lid] : 3.402823466e+38f;
        mx = (lid < nw) ? s_mx[lid] : -3.402823466e+38f;
        #pragma unroll
        for (int off = 4; off > 0; off >>= 1) {
            mn = fminf(mn, __shfl_xor_sync(0xFFFFFFFFu, mn, off));
            mx = fmaxf(mx, __shfl_xor_sync(0xFFFFFFFFu, mx, off));
        }
        if (lid == 0) {
            atomicMin(&g_min_bits, flip_f2u(mn));
            atomicMax(&g_max_bits, flip_f2u(mx));
        }
    }
}

// ---------------- apply: backward sweep, 4-wide, 1184 blocks ----------------
__global__ void __launch_bounds__(TPB) fakequant_apply_kernel(
    const float4* __restrict__ x4, float4* __restrict__ out4, int n4,
    const float* __restrict__ x, float* __restrict__ out, int n) {
    // Read global min/max (2 words, L2-broadcast; kernel boundary ordered
    // them after all reduce-side atomics).
    const float mn = unflip_u2f(g_min_bits);
    const float mx = unflip_u2f(g_max_bits);
    const float scale = 255.0f / (mx - mn);
    const float inv   = 1.0f / scale;

    const int S = gridDim.x * blockDim.x;
    const int gtid = blockIdx.x * blockDim.x + threadIdx.x;

    if (gtid < n4) {
        int k = (n4 - 1 - gtid) / S;  // highest valid stride index

        for (; k >= 3; k -= 4) {
            int i0 = gtid + k * S;
            int i1 = i0 - S;
            int i2 = i0 - 2 * S;
            int i3 = i0 - 3 * S;
            float4 a = __ldcs(&x4[i0]);
            float4 b = __ldcs(&x4[i1]);
            float4 c = __ldcs(&x4[i2]);
            float4 d = __ldcs(&x4[i3]);
            __stcs(&out4[i0], fq4(a, mn, scale, inv));
            __stcs(&out4[i1], fq4(b, mn, scale, inv));
            __stcs(&out4[i2], fq4(c, mn, scale, inv));
            __stcs(&out4[i3], fq4(d, mn, scale, inv));
        }
        for (; k >= 0; --k) {
            int i0 = gtid + k * S;
            __stcs(&out4[i0], fq4(__ldcs(&x4[i0]), mn, scale, inv));
        }
    }

    // Scalar tail (n % 4 != 0; never hit for this shape). Done before the
    // done-counter increment so the sentinel reset stays ordered after it.
    int tail_start = n4 << 2;
    if (blockIdx.x == 0) {
        for (int i = tail_start + threadIdx.x; i < n; i += TPB)
            out[i] = fmaf(rintf((x[i] - mn) * scale), inv, mn);
    }

    // Last-finishing block restores the sentinels for the next graph replay.
    __syncthreads();
    if (threadIdx.x == 0) {
        unsigned int prev = atomicAdd(&g_app_done, 1u);
        if (prev == (unsigned int)(gridDim.x - 1)) {
            g_app_done = 0;
            g_min_bits = 0xFFFFFFFFu;
            g_max_bits = 0x00000000u;
        }
    }
}

extern "C" void kernel_launch(void* const* d_in, const int* in_sizes, int n_in,
                              void* d_out, int out_size) {
    const float* x = (const float*)d_in[0];
    float* out = (float*)d_out;
    int n = in_sizes[0];
    int n4 = n >> 2;

    // Keep the TOP ~112MB of x default-policy in reduce (L2 is ~126MB).
    const long long KEEP_BYTES = 112LL * 1024 * 1024;
    int keep_elems = (int)(KEEP_BYTES / 16);  // float4s
    int keep_thresh = n4 > keep_elems ? n4 - keep_elems : 0;

    minmax_reduce_kernel<<<RED_BLOCKS, TPB>>>((const float4*)x, n4, keep_thresh);
    fakequant_apply_kernel<<<APP_BLOCKS, TPB>>>((const float4*)x, (float4*)out,
                                                n4, x, out, n);
}